// round 10
// baseline (speedup 1.0000x reference)
#include <cuda_runtime.h>
#include <cuda_fp16.h>
#include <math.h>
#include <stdint.h>

#define N_PIX   131072
#define TAU     0.002f
#define INV2048 4.8828125e-4f

// Output layout offsets (flattened tuple, float32) — total 8651778
#define QUANT_OFF 0
#define LOSS_OFF  8388608
#define PERP_OFF  8388609
#define IDX_OFF   8388610
#define NCS_OFF   8519682
#define NEMA_OFF  8520706
#define NEMB_OFF  8586242

// Scratch (device globals; no allocation allowed)
__device__ int   g_idx[N_PIX];
__device__ float g_esqh[1024];                       // -0.5*||e||^2
__device__ float g_counts[1024];
__device__ float g_dwp[8 * 65536];                   // 8-way privatized dw
__device__ float g_scl[1024];
__device__ float g_loss;
// packed split-fp16 codebook: [chunk 16][split 2][kstep 4][n 64][j 8] half2
// lo entries pre-scaled by 2048
__device__ __align__(128) __half g_Bpk[16 * 8192];
__device__ int   g_fb_list[N_PIX];
__device__ int   g_fb_count;
__device__ int   g_fb_take;

// ---------------------------------------------------------------------------
// helpers (base PTX only)
// ---------------------------------------------------------------------------
__device__ __forceinline__ uint32_t smem_u32(const void* p) {
    uint32_t a;
    asm("{ .reg .u64 t; cvta.to.shared.u64 t, %1; cvt.u32.u64 %0, t; }" : "=r"(a) : "l"(p));
    return a;
}
__device__ __forceinline__ void mma16(float& d0, float& d1, float& d2, float& d3,
                                      const uint32_t* a, uint32_t b0, uint32_t b1) {
    asm volatile(
        "mma.sync.aligned.m16n8k16.row.col.f32.f16.f16.f32 "
        "{%0,%1,%2,%3}, {%4,%5,%6,%7}, {%8,%9}, {%0,%1,%2,%3};"
        : "+f"(d0), "+f"(d1), "+f"(d2), "+f"(d3)
        : "r"(a[0]), "r"(a[1]), "r"(a[2]), "r"(a[3]), "r"(b0), "r"(b1));
}
// f16-accumulated variant (correction terms; double-rate on most HW)
__device__ __forceinline__ void mma16h(uint32_t& d0, uint32_t& d1,
                                       const uint32_t* a, uint32_t b0, uint32_t b1) {
    asm volatile(
        "mma.sync.aligned.m16n8k16.row.col.f16.f16.f16.f16 "
        "{%0,%1}, {%2,%3,%4,%5}, {%6,%7}, {%0,%1};"
        : "+r"(d0), "+r"(d1)
        : "r"(a[0]), "r"(a[1]), "r"(a[2]), "r"(a[3]), "r"(b0), "r"(b1));
}
#define CP_ASYNC16(dst, src) \
    asm volatile("cp.async.cg.shared.global [%0], [%1], 16;" :: "r"(dst), "l"(src) : "memory")
#define CP_COMMIT() asm volatile("cp.async.commit_group;" ::: "memory")
#define CP_WAIT1()  asm volatile("cp.async.wait_group 1;" ::: "memory")
#define CP_WAIT0()  asm volatile("cp.async.wait_group 0;" ::: "memory")

__device__ __forceinline__ void red_v4(float* p, float a, float b, float c, float d) {
    asm volatile("red.global.add.v4.f32 [%0], {%1,%2,%3,%4};"
                 :: "l"(p), "f"(a), "f"(b), "f"(c), "f"(d) : "memory");
}

// split x into f16 hi + f16 lo*2048 (pair-packed)
__device__ __forceinline__ uint32_t packsplit(float x0, float x1, uint32_t& lo) {
    __half h0 = __float2half_rn(x0), h1 = __float2half_rn(x1);
    __half l0 = __float2half_rn((x0 - __half2float(h0)) * 2048.0f);
    __half l1 = __float2half_rn((x1 - __half2float(h1)) * 2048.0f);
    __half2 hh = __halves2half2(h0, h1), ll = __halves2half2(l0, l1);
    lo = *(uint32_t*)&ll;
    return *(uint32_t*)&hh;
}
// best-2 running update (strict > keeps lowest index; codes ascend)
__device__ __forceinline__ void upd(float& b1, int& i1, float& b2, float s, int idx) {
    if (s > b1) { b2 = b1; b1 = s; i1 = idx; }
    else if (s > b2) { b2 = s; }
}

// ---------------------------------------------------------------------------
// Kernel 1: prep — split-fp16 packed codebook (lo*2048), esqh, zero accums
// grid 1024 (code k), 64 threads (channel d)
// ---------------------------------------------------------------------------
__global__ void prep_kernel(const float* __restrict__ embed) {
    int k = blockIdx.x;
    int t = threadIdx.x;
    float v = embed[k * 64 + t];
    #pragma unroll
    for (int i = 0; i < 8; i++) g_dwp[i * 65536 + k * 64 + t] = 0.0f;

    __half hi = __float2half_rn(v);
    __half lo = __float2half_rn((v - __half2float(hi)) * 2048.0f);
    // pack layout: halves index = chunk*8192 + ((split*4+s)*64+n)*16 + j*2 + h
    // pair p covers k_local = 16s + 2p..+1 ; j order {0,4,1,5,2,6,3,7}
    int c = k >> 6, n = k & 63, s = t >> 4, dl = t & 15, p = dl >> 1, h = dl & 1;
    int j = ((p & 3) << 1) | (p >> 2);
    int base = c * 8192;
    g_Bpk[base + (s * 64 + n) * 16 + j * 2 + h] = hi;
    g_Bpk[base + ((4 + s) * 64 + n) * 16 + j * 2 + h] = lo;

    float sq = v * v;
    #pragma unroll
    for (int o = 16; o; o >>= 1) sq += __shfl_down_sync(0xffffffffu, sq, o);
    __shared__ float sm[2];
    if ((t & 31) == 0) sm[t >> 5] = sq;
    __syncthreads();
    if (t == 0) {
        g_esqh[k] = -0.5f * (sm[0] + sm[1]);
        g_counts[k] = 0.0f;
        if (k == 0) { g_loss = 0.0f; g_fb_count = 0; g_fb_take = 0; }
    }
}

// ---------------------------------------------------------------------------
// Kernel 2: split-FP16 argmin via mma.sync m16n8k16.
// hi*hi in f32 accum; (lo*hi + hi*lo) scaled 2^11 in shared f16 accum.
// 1024 blocks x 256 threads; block = 128 pixels; codes in 16 chunks of 64.
// Tracks s = x.e - 0.5*||e||^2 ; argmin dist == argmax s.
// ---------------------------------------------------------------------------
__global__ void __launch_bounds__(256) argmin_mma(const float* __restrict__ in,
                                                  float* __restrict__ out) {
    __shared__ __align__(16) __half Bsm[16384];   // 2 bufs x 16KB
    __shared__ float esqs[1024];
    uint32_t smb = smem_u32(Bsm);

    const int tid = threadIdx.x;
    const int w   = tid >> 5;
    const int ln  = tid & 31;
    const int g   = ln >> 2;
    const int t   = ln & 3;
    const int p0  = blockIdx.x * 128;
    const int bimg = p0 >> 12;
    const int hw0  = p0 & 4095;

    // chunk 0 -> buf 0
    #pragma unroll
    for (int jj = 0; jj < 4; jj++) {
        int idx = tid + jj * 256;
        CP_ASYNC16(smb + idx * 16, (const char*)g_Bpk + idx * 16);
    }
    CP_COMMIT();

    #pragma unroll
    for (int i = 0; i < 4; i++) esqs[tid + i * 256] = g_esqh[tid + i * 256];

    // A fragments: 16 pixels x 64 ch, split fp16, in registers
    uint32_t ah[4][4], al[4][4];
    {
        const float* ap = in + (size_t)bimg * 262144 + hw0 + w * 16 + g;
        #pragma unroll
        for (int s = 0; s < 4; s++) {
            int d0 = 16 * s + 2 * t;
            ah[s][0] = packsplit(ap[d0 * 4096],          ap[(d0 + 1) * 4096],     al[s][0]); // row g
            ah[s][1] = packsplit(ap[d0 * 4096 + 8],      ap[(d0 + 1) * 4096 + 8], al[s][1]); // row g+8
            ah[s][2] = packsplit(ap[(d0 + 8) * 4096],    ap[(d0 + 9) * 4096],     al[s][2]);
            ah[s][3] = packsplit(ap[(d0 + 8) * 4096 + 8],ap[(d0 + 9) * 4096 + 8], al[s][3]);
        }
    }

    float b1a = -3.4e38f, b2a = -3.4e38f; int i1a = 0;   // pixel row g
    float b1b = -3.4e38f, b2b = -3.4e38f; int i1b = 0;   // pixel row g+8

    for (int c = 0; c < 16; c++) {
        const int buf = c & 1;
        if (c < 15) {
            int nb = (c + 1) & 1;
            #pragma unroll
            for (int jj = 0; jj < 4; jj++) {
                int idx = tid + jj * 256;
                CP_ASYNC16(smb + nb * 16384 + idx * 16,
                           (const char*)g_Bpk + (c + 1) * 16384 + idx * 16);
            }
            CP_COMMIT();
            CP_WAIT1();
        } else {
            CP_WAIT0();
        }
        __syncthreads();

        const uint32_t bb = smb + buf * 16384;
        const int kbase = c * 64;

        #pragma unroll
        for (int nt = 0; nt < 8; nt++) {
            float c0 = 0.f, c1 = 0.f, c2 = 0.f, c3 = 0.f;
            uint32_t h0 = 0u, h1 = 0u;                   // f16 correction accum
            const int nb_ = nt * 8 + g;
            #pragma unroll
            for (int s = 0; s < 4; s++) {
                uint32_t offh = bb + (s * 64 + nb_) * 32 + 8 * t;
                uint32_t offl = offh + 8192;             // split=1 half of chunk
                uint32_t bh0, bh1, bl0, bl1;
                asm volatile("ld.shared.v2.b32 {%0,%1}, [%2];" : "=r"(bh0), "=r"(bh1) : "r"(offh));
                asm volatile("ld.shared.v2.b32 {%0,%1}, [%2];" : "=r"(bl0), "=r"(bl1) : "r"(offl));
                mma16(c0, c1, c2, c3, ah[s], bh0, bh1);  // hi*hi, f32 accum
                mma16h(h0, h1, al[s], bh0, bh1);         // (2^11 lo)*hi, f16 accum
                mma16h(h0, h1, ah[s], bl0, bl1);         // hi*(2^11 lo), f16 accum
            }
            float2 f0 = __half22float2(*reinterpret_cast<__half2*>(&h0));
            float2 f1 = __half22float2(*reinterpret_cast<__half2*>(&h1));
            c0 += f0.x * INV2048; c1 += f0.y * INV2048;
            c2 += f1.x * INV2048; c3 += f1.y * INV2048;

            int code0 = kbase + nt * 8 + 2 * t;
            float e0 = esqs[code0], e1 = esqs[code0 + 1];
            upd(b1a, i1a, b2a, c0 + e0, code0);
            upd(b1a, i1a, b2a, c1 + e1, code0 + 1);
            upd(b1b, i1b, b2b, c2 + e0, code0);
            upd(b1b, i1b, b2b, c3 + e1, code0 + 1);
        }
        __syncthreads();
    }

    // reduce across the 4 lanes of the group (t = 0..3)
    #pragma unroll
    for (int o = 1; o <= 2; o <<= 1) {
        float ob1 = __shfl_xor_sync(0xffffffffu, b1a, o);
        float ob2 = __shfl_xor_sync(0xffffffffu, b2a, o);
        int   oi1 = __shfl_xor_sync(0xffffffffu, i1a, o);
        if (ob1 > b1a || (ob1 == b1a && oi1 < i1a)) { b2a = fmaxf(b1a, ob2); b1a = ob1; i1a = oi1; }
        else { b2a = fmaxf(b2a, ob1); }
        ob1 = __shfl_xor_sync(0xffffffffu, b1b, o);
        ob2 = __shfl_xor_sync(0xffffffffu, b2b, o);
        oi1 = __shfl_xor_sync(0xffffffffu, i1b, o);
        if (ob1 > b1b || (ob1 == b1b && oi1 < i1b)) { b2b = fmaxf(b1b, ob2); b1b = ob1; i1b = oi1; }
        else { b2b = fmaxf(b2b, ob1); }
    }

    if (t == 0) {
        int n = p0 + w * 16 + g;
        g_idx[n] = i1a;
        out[IDX_OFF + n] = (float)i1a;
        if (b1a - b2a < TAU) g_fb_list[atomicAdd(&g_fb_count, 1)] = n;
        int n2 = n + 8;
        g_idx[n2] = i1b;
        out[IDX_OFF + n2] = (float)i1b;
        if (b1b - b2b < TAU) g_fb_list[atomicAdd(&g_fb_count, 1)] = n2;
    }
}

// ---------------------------------------------------------------------------
// Kernel 2b: exact fp32 fallback for ambiguous pixels
// ---------------------------------------------------------------------------
__global__ void fb_kernel(const float* __restrict__ in,
                          const float* __restrict__ embed,
                          float* __restrict__ out) {
    __shared__ float xs[64];
    __shared__ float rv[256];
    __shared__ int   ri[256];
    __shared__ int   cur;
    while (true) {
        if (threadIdx.x == 0) cur = atomicAdd(&g_fb_take, 1);
        __syncthreads();
        int i = cur;
        if (i >= g_fb_count) break;
        int n = g_fb_list[i];
        int b = n >> 12, hw = n & 4095;
        if (threadIdx.x < 64)
            xs[threadIdx.x] = in[(size_t)b * 262144 + threadIdx.x * 4096 + hw];
        __syncthreads();

        int k0 = threadIdx.x * 4;
        float bv = -3.4e38f; int bi = 0;
        for (int k = k0; k < k0 + 4; k++) {
            const float* e = embed + k * 64;
            float s = g_esqh[k];
            #pragma unroll
            for (int c = 0; c < 64; c++) s = fmaf(xs[c], e[c], s);
            if (s > bv) { bv = s; bi = k; }
        }
        rv[threadIdx.x] = bv; ri[threadIdx.x] = bi;
        __syncthreads();
        for (int o = 128; o; o >>= 1) {
            if (threadIdx.x < o) {
                float v2 = rv[threadIdx.x + o]; int i2 = ri[threadIdx.x + o];
                if (v2 > rv[threadIdx.x] || (v2 == rv[threadIdx.x] && i2 < ri[threadIdx.x])) {
                    rv[threadIdx.x] = v2; ri[threadIdx.x] = i2;
                }
            }
            __syncthreads();
        }
        if (threadIdx.x == 0) { g_idx[n] = ri[0]; out[IDX_OFF + n] = (float)ri[0]; }
        __syncthreads();
    }
}

// ---------------------------------------------------------------------------
// Kernel 3: quantize — 2 threads per pixel (32 channels each);
// contiguous embed-row gather, coalesced in/out, privatized v4 REDs.
// ---------------------------------------------------------------------------
__global__ void quant_kernel(const float* __restrict__ in,
                             const float* __restrict__ embed,
                             float* __restrict__ out) {
    int idx = blockIdx.x * 256 + threadIdx.x;     // 0..262143
    int n = idx >> 1, sub = idx & 1;              // pixel, half
    int b = n >> 12, hw = n & 4095;
    int r = g_idx[n];

    const float4* er = (const float4*)(embed + r * 64) + sub * 8;
    const float* ib = in + (size_t)b * 262144 + hw + (size_t)sub * 32 * 4096;
    float* ob = out + QUANT_OFF + (size_t)b * 262144 + hw + (size_t)sub * 32 * 4096;
    float* dwr = g_dwp + (blockIdx.x & 7) * 65536 + r * 64 + sub * 32;

    float s = 0.0f;
    #pragma unroll
    for (int j = 0; j < 8; j++) {
        float4 q = __ldg(er + j);
        int d = j * 4;
        float x0 = ib[(size_t)d * 4096];
        float x1 = ib[(size_t)(d + 1) * 4096];
        float x2 = ib[(size_t)(d + 2) * 4096];
        float x3 = ib[(size_t)(d + 3) * 4096];
        ob[(size_t)d * 4096]       = q.x;
        ob[(size_t)(d + 1) * 4096] = q.y;
        ob[(size_t)(d + 2) * 4096] = q.z;
        ob[(size_t)(d + 3) * 4096] = q.w;
        float e0 = q.x - x0, e1 = q.y - x1, e2 = q.z - x2, e3 = q.w - x3;
        s += e0 * e0 + e1 * e1 + e2 * e2 + e3 * e3;
        red_v4(dwr + d, x0, x1, x2, x3);
    }
    if (sub == 0) atomicAdd(&g_counts[r], 1.0f);

    #pragma unroll
    for (int o = 16; o; o >>= 1) s += __shfl_down_sync(0xffffffffu, s, o);
    __shared__ float sm[8];
    if ((threadIdx.x & 31) == 0) sm[threadIdx.x >> 5] = s;
    __syncthreads();
    if (threadIdx.x == 0) {
        float tot = 0.0f;
        #pragma unroll
        for (int i = 0; i < 8; i++) tot += sm[i];
        atomicAdd(&g_loss, tot);
    }
}

// ---------------------------------------------------------------------------
// Kernel 4a: scalars
// ---------------------------------------------------------------------------
__global__ void scalar_kernel(const float* __restrict__ ema_cs, float* __restrict__ out) {
    __shared__ float s1[1024];
    __shared__ float s2[1024];
    int k = threadIdx.x;
    float cnt = g_counts[k];
    float ncs = 0.99f * ema_cs[k] + 0.01f * cnt;
    out[NCS_OFF + k] = ncs;
    float p = cnt * (1.0f / 131072.0f);
    s1[k] = ncs;
    s2[k] = p * logf(p + 1e-10f);
    __syncthreads();
    for (int o = 512; o; o >>= 1) {
        if (k < o) { s1[k] += s1[k + o]; s2[k] += s2[k + o]; }
        __syncthreads();
    }
    float nsum = s1[0];
    float csz = (ncs + 1e-5f) / (nsum + 1024.0f * 1e-5f) * nsum;
    g_scl[k] = fmaxf(csz, 1e-5f);
    if (k == 0) {
        out[LOSS_OFF] = 0.25f * g_loss * (1.0f / 8388608.0f);
        out[PERP_OFF] = expf(-s2[0]);
    }
}

// ---------------------------------------------------------------------------
// Kernel 4b: wide EMA update (sums the 8 dw replicas)
// ---------------------------------------------------------------------------
__global__ void ema_kernel(const float* __restrict__ ema_w, float* __restrict__ out) {
    int e = blockIdx.x * 512 + threadIdx.x;       // 0..65535
    int kk = e >> 6;
    float dw = 0.0f;
    #pragma unroll
    for (int i = 0; i < 8; i++) dw += g_dwp[i * 65536 + e];
    float w = 0.99f * ema_w[e] + 0.01f * dw;
    out[NEMA_OFF + e] = w;
    out[NEMB_OFF + e] = w / g_scl[kk];
}

// ---------------------------------------------------------------------------
extern "C" void kernel_launch(void* const* d_in, const int* in_sizes, int n_in,
                              void* d_out, int out_size) {
    const float* in    = (const float*)d_in[0];
    const float* embed = (const float*)d_in[1];
    const float* ecs   = (const float*)d_in[2];
    const float* emw   = (const float*)d_in[3];
    float* out = (float*)d_out;

    prep_kernel<<<1024, 64>>>(embed);
    argmin_mma<<<1024, 256>>>(in, out);
    fb_kernel<<<296, 256>>>(in, embed, out);
    quant_kernel<<<1024, 256>>>(in, embed, out);
    scalar_kernel<<<1, 1024>>>(ecs, out);
    ema_kernel<<<128, 512>>>(emw, out);
}